// round 8
// baseline (speedup 1.0000x reference)
#include <cuda_runtime.h>
#include <cuda_bf16.h>
#include <stdint.h>

// Problem dims (fixed by the reference)
#define B_  8
#define N_  2048
#define H_  128
#define R_  (B_ * N_)   // 16384 total rows

// GEMM tiling
#define BM 128
#define BN 128
#define BK 32
#define KP 40           // padded K stride in smem (bf16 elems) -> conflict-free frag loads
#define NTHREADS 256

// -------- scratch (__device__ globals: no allocation allowed) --------
__device__ float g_m1 [R_ * H_];        // 8 MB
__device__ float g_m2 [R_ * H_];        // 8 MB
__device__ float g_mt [B_ * H_ * N_];   // 8 MB   (m2 transposed per batch: [b][h][n])
__device__ float g_msg[R_ * H_];        // 8 MB
__device__ float g_gx [R_ * 3 * H_];    // 24 MB
__device__ float g_gh [R_ * 3 * H_];    // 24 MB

__device__ __forceinline__ uint32_t lds_u32(const __nv_bfloat16* p) {
    return *reinterpret_cast<const uint32_t*>(p);
}

__device__ __forceinline__ void mma_bf16(float* c,
                                         uint32_t a0, uint32_t a1, uint32_t a2, uint32_t a3,
                                         uint32_t b0, uint32_t b1) {
    asm volatile(
        "mma.sync.aligned.m16n8k16.row.col.f32.bf16.bf16.f32 "
        "{%0,%1,%2,%3}, {%4,%5,%6,%7}, {%8,%9}, {%0,%1,%2,%3};\n"
        : "+f"(c[0]), "+f"(c[1]), "+f"(c[2]), "+f"(c[3])
        : "r"(a0), "r"(a1), "r"(a2), "r"(a3), "r"(b0), "r"(b1));
}

// C[M x N] = act( A[M x K] * B[N x K]^T + bias ), fp32 in/out.
// Internally: 2-term bf16 split per operand, 3 bf16 MMAs (hi*hi + hi*lo + lo*hi),
// fp32 accumulate -> effectively fp32-precision GEMM on tensor cores.
// Requirements (all satisfied here): M%128==0, N%128==0, K%32==0, 16B-aligned rows.
template<int ACT>
__global__ void __launch_bounds__(NTHREADS, 1)
gemm_nt_split(const float* __restrict__ A, long long strideA, int lda,
              const float* __restrict__ Bm, long long strideB, int ldb,
              const float* __restrict__ bias,
              float* __restrict__ C, long long strideC, int ldc,
              int K)
{
    __shared__ __nv_bfloat16 sAhi[BM * KP];
    __shared__ __nv_bfloat16 sAlo[BM * KP];
    __shared__ __nv_bfloat16 sBhi[BN * KP];
    __shared__ __nv_bfloat16 sBlo[BN * KP];

    const int tid  = threadIdx.x;
    const int lane = tid & 31;
    const int warp = tid >> 5;
    const int wm   = warp >> 2;     // 0..1  -> warp row 0/64
    const int wn   = warp & 3;      // 0..3  -> warp col 0/32/64/96
    const int wrow = wm * 64;
    const int wcol = wn * 32;

    const long long bz = blockIdx.z;
    const float* Ag = A  + bz * strideA + (long long)blockIdx.y * BM * lda;
    const float* Bg = Bm + bz * strideB + (long long)blockIdx.x * BN * ldb;

    // global->smem loader mapping: 1024 float4 per tile pair, 4 per thread
    const int lr = tid >> 3;         // row 0..31 (+32p)
    const int lc = (tid & 7) * 4;    // float col 0..28

    float acc[4][4][4];
    #pragma unroll
    for (int i = 0; i < 4; i++)
        #pragma unroll
        for (int j = 0; j < 4; j++)
            #pragma unroll
            for (int t = 0; t < 4; t++) acc[i][j][t] = 0.f;

    const int arow = lane >> 2;        // 0..7
    const int kq   = (lane & 3) * 2;   // 0,2,4,6

    for (int k0 = 0; k0 < K; k0 += BK) {
        float4 ra[4], rb[4];
        #pragma unroll
        for (int p = 0; p < 4; p++) {
            ra[p] = *reinterpret_cast<const float4*>(Ag + (long long)(lr + 32 * p) * lda + (k0 + lc));
            rb[p] = *reinterpret_cast<const float4*>(Bg + (long long)(lr + 32 * p) * ldb + (k0 + lc));
        }
        __syncthreads();   // previous iteration's compute done reading smem
        #pragma unroll
        for (int p = 0; p < 4; p++) {
            const int off = (lr + 32 * p) * KP + lc;
            float va[4] = {ra[p].x, ra[p].y, ra[p].z, ra[p].w};
            float vb[4] = {rb[p].x, rb[p].y, rb[p].z, rb[p].w};
            __nv_bfloat16 hi[4], lo[4];
            #pragma unroll
            for (int q = 0; q < 4; q++) {
                hi[q] = __float2bfloat16(va[q]);
                lo[q] = __float2bfloat16(va[q] - __bfloat162float(hi[q]));
            }
            *reinterpret_cast<__nv_bfloat162*>(sAhi + off)     = __halves2bfloat162(hi[0], hi[1]);
            *reinterpret_cast<__nv_bfloat162*>(sAhi + off + 2) = __halves2bfloat162(hi[2], hi[3]);
            *reinterpret_cast<__nv_bfloat162*>(sAlo + off)     = __halves2bfloat162(lo[0], lo[1]);
            *reinterpret_cast<__nv_bfloat162*>(sAlo + off + 2) = __halves2bfloat162(lo[2], lo[3]);
            #pragma unroll
            for (int q = 0; q < 4; q++) {
                hi[q] = __float2bfloat16(vb[q]);
                lo[q] = __float2bfloat16(vb[q] - __bfloat162float(hi[q]));
            }
            *reinterpret_cast<__nv_bfloat162*>(sBhi + off)     = __halves2bfloat162(hi[0], hi[1]);
            *reinterpret_cast<__nv_bfloat162*>(sBhi + off + 2) = __halves2bfloat162(hi[2], hi[3]);
            *reinterpret_cast<__nv_bfloat162*>(sBlo + off)     = __halves2bfloat162(lo[0], lo[1]);
            *reinterpret_cast<__nv_bfloat162*>(sBlo + off + 2) = __halves2bfloat162(lo[2], lo[3]);
        }
        __syncthreads();   // smem tiles ready

        #pragma unroll
        for (int kk = 0; kk < BK; kk += 16) {
            uint32_t ah[4][4], al[4][4];
            #pragma unroll
            for (int i = 0; i < 4; i++) {
                const int base = (wrow + i * 16 + arow) * KP + kk + kq;
                ah[i][0] = lds_u32(sAhi + base);
                ah[i][1] = lds_u32(sAhi + base + 8 * KP);
                ah[i][2] = lds_u32(sAhi + base + 8);
                ah[i][3] = lds_u32(sAhi + base + 8 * KP + 8);
                al[i][0] = lds_u32(sAlo + base);
                al[i][1] = lds_u32(sAlo + base + 8 * KP);
                al[i][2] = lds_u32(sAlo + base + 8);
                al[i][3] = lds_u32(sAlo + base + 8 * KP + 8);
            }
            uint32_t bh[4][2], bl[4][2];
            #pragma unroll
            for (int j = 0; j < 4; j++) {
                const int base = (wcol + j * 8 + arow) * KP + kk + kq;
                bh[j][0] = lds_u32(sBhi + base);
                bh[j][1] = lds_u32(sBhi + base + 8);
                bl[j][0] = lds_u32(sBlo + base);
                bl[j][1] = lds_u32(sBlo + base + 8);
            }
            #pragma unroll
            for (int i = 0; i < 4; i++)
                #pragma unroll
                for (int j = 0; j < 4; j++) {
                    mma_bf16(acc[i][j], ah[i][0], ah[i][1], ah[i][2], ah[i][3], bh[j][0], bh[j][1]);
                    mma_bf16(acc[i][j], ah[i][0], ah[i][1], ah[i][2], ah[i][3], bl[j][0], bl[j][1]);
                    mma_bf16(acc[i][j], al[i][0], al[i][1], al[i][2], al[i][3], bh[j][0], bh[j][1]);
                }
        }
    }

    // epilogue: bias + optional relu, fp32 store
    float* Cg = C + bz * strideC;
    const int rb0 = blockIdx.y * BM + wrow;
    const int cb0 = blockIdx.x * BN + wcol;
    #pragma unroll
    for (int i = 0; i < 4; i++) {
        const int r0 = rb0 + i * 16 + (lane >> 2);
        #pragma unroll
        for (int j = 0; j < 4; j++) {
            const int c0 = cb0 + j * 8 + (lane & 3) * 2;
            float v0 = acc[i][j][0], v1 = acc[i][j][1], v2 = acc[i][j][2], v3 = acc[i][j][3];
            if (bias) {
                const float bb0 = bias[c0], bb1 = bias[c0 + 1];
                v0 += bb0; v1 += bb1; v2 += bb0; v3 += bb1;
            }
            if (ACT) {
                v0 = fmaxf(v0, 0.f); v1 = fmaxf(v1, 0.f);
                v2 = fmaxf(v2, 0.f); v3 = fmaxf(v3, 0.f);
            }
            *reinterpret_cast<float2*>(Cg + (long long)r0 * ldc + c0)       = make_float2(v0, v1);
            *reinterpret_cast<float2*>(Cg + (long long)(r0 + 8) * ldc + c0) = make_float2(v2, v3);
        }
    }
}

// transpose m2 [b][n][h] -> mt [b][h][n]   (so the adjacency gemm is also NT)
__global__ void transpose_m(const float* __restrict__ src, float* __restrict__ dst)
{
    __shared__ float t[32][33];
    const int b  = blockIdx.z;
    const int n0 = blockIdx.x * 32;
    const int h0 = blockIdx.y * 32;
    const float* s = src + (long long)b * N_ * H_;
    float* d       = dst + (long long)b * H_ * N_;
    const int tx = threadIdx.x, ty = threadIdx.y;  // 32 x 8
    #pragma unroll
    for (int i = 0; i < 32; i += 8)
        t[ty + i][tx] = s[(long long)(n0 + ty + i) * H_ + h0 + tx];
    __syncthreads();
    #pragma unroll
    for (int i = 0; i < 32; i += 8)
        d[(long long)(h0 + ty + i) * N_ + n0 + tx] = t[tx][ty + i];
}

// GRU gate combine: r,z,n gates (torch GRUCell order) -> out
__global__ void gru_gates(const float* __restrict__ gx, const float* __restrict__ gh,
                          const float* __restrict__ h, float* __restrict__ out)
{
    const int idx = blockIdx.x * blockDim.x + threadIdx.x;
    if (idx >= R_ * H_) return;
    const int i = idx >> 7;      // row
    const int j = idx & (H_ - 1);
    const float* gxr = gx + (long long)i * 3 * H_;
    const float* ghr = gh + (long long)i * 3 * H_;
    const float r = 1.f / (1.f + expf(-(gxr[j]           + ghr[j])));
    const float z = 1.f / (1.f + expf(-(gxr[j + H_]      + ghr[j + H_])));
    const float n = tanhf(gxr[j + 2 * H_] + r * ghr[j + 2 * H_]);
    out[idx] = (1.f - z) * n + z * h[idx];
}

extern "C" void kernel_launch(void* const* d_in, const int* in_sizes, int n_in,
                              void* d_out, int out_size)
{
    const float* h   = (const float*)d_in[0];   // [8,2048,128]
    const float* A   = (const float*)d_in[1];   // [8,2048,2048]
    const float* W1  = (const float*)d_in[2];   // [128,128]
    const float* b1  = (const float*)d_in[3];   // [128]
    const float* W2  = (const float*)d_in[4];   // [128,128]
    const float* b2  = (const float*)d_in[5];   // [128]
    const float* Wih = (const float*)d_in[6];   // [384,128]
    const float* Whh = (const float*)d_in[7];   // [384,128]
    const float* bih = (const float*)d_in[8];   // [384]
    const float* bhh = (const float*)d_in[9];   // [384]
    float* out = (float*)d_out;                 // [8,2048,128]

    float *m1, *m2, *mt, *msg, *gx, *gh;
    cudaGetSymbolAddress((void**)&m1,  g_m1);
    cudaGetSymbolAddress((void**)&m2,  g_m2);
    cudaGetSymbolAddress((void**)&mt,  g_mt);
    cudaGetSymbolAddress((void**)&msg, g_msg);
    cudaGetSymbolAddress((void**)&gx,  g_gx);
    cudaGetSymbolAddress((void**)&gh,  g_gh);

    const dim3 blk(NTHREADS);

    // 1) m1 = relu(h @ W1^T + b1)      [16384 x 128] = [16384 x 128] x [128 x 128]^T
    gemm_nt_split<1><<<dim3(1, R_ / BM, 1), blk>>>(
        h, 0, H_, W1, 0, H_, b1, m1, 0, H_, H_);

    // 2) m2 = relu(m1 @ W2^T + b2)
    gemm_nt_split<1><<<dim3(1, R_ / BM, 1), blk>>>(
        m1, 0, H_, W2, 0, H_, b2, m2, 0, H_, H_);

    // 3) mt[b][h][n] = m2[b][n][h]
    transpose_m<<<dim3(N_ / 32, H_ / 32, B_), dim3(32, 8)>>>(m2, mt);

    // 4) msg = relu(A_b @ m_b)  per batch: M=2048, N=128, K=2048 (NT vs mt)
    gemm_nt_split<1><<<dim3(1, N_ / BM, B_), blk>>>(
        A,  (long long)N_ * N_, N_,
        mt, (long long)H_ * N_, N_,
        nullptr,
        msg, (long long)N_ * H_, H_, N_);

    // 5) gx = msg @ W_ih^T + b_ih   [16384 x 384]
    gemm_nt_split<0><<<dim3(3 * H_ / BN, R_ / BM, 1), blk>>>(
        msg, 0, H_, Wih, 0, H_, bih, gx, 0, 3 * H_, H_);

    // 6) gh = h @ W_hh^T + b_hh
    gemm_nt_split<0><<<dim3(3 * H_ / BN, R_ / BM, 1), blk>>>(
        h, 0, H_, Whh, 0, H_, bhh, gh, 0, 3 * H_, H_);

    // 7) gates + output
    gru_gates<<<(R_ * H_ + 255) / 256, 256>>>(gx, gh, h, out);
}

// round 9
// speedup vs baseline: 1.3121x; 1.3121x over previous
#include <cuda_runtime.h>
#include <cuda_bf16.h>
#include <stdint.h>

// Problem dims (fixed by the reference)
#define B_  8
#define N_  2048
#define H_  128
#define R_  (B_ * N_)   // 16384 total rows

// GEMM tiling
#define BM 128
#define BN 128
#define BK 32
#define KP 40           // padded K stride (bf16) for BK=32 tiles -> conflict-free
#define KP2 136         // padded K stride (bf16) for K=128 resident tiles
#define NTHREADS 256

// -------- scratch (__device__ globals: no allocation allowed) --------
__device__ float g_m2 [R_ * H_];        // 8 MB
__device__ float g_mt [B_ * H_ * N_];   // 8 MB   (m2 transposed per batch: [b][h][n])
__device__ float g_msg[R_ * H_];        // 8 MB
__device__ float g_gx [R_ * 3 * H_];    // 24 MB
__device__ float g_gh [R_ * 3 * H_];    // 24 MB

__device__ __forceinline__ uint32_t lds_u32(const __nv_bfloat16* p) {
    return *reinterpret_cast<const uint32_t*>(p);
}

__device__ __forceinline__ void mma_bf16(float* c,
                                         uint32_t a0, uint32_t a1, uint32_t a2, uint32_t a3,
                                         uint32_t b0, uint32_t b1) {
    asm volatile(
        "mma.sync.aligned.m16n8k16.row.col.f32.bf16.bf16.f32 "
        "{%0,%1,%2,%3}, {%4,%5,%6,%7}, {%8,%9}, {%0,%1,%2,%3};\n"
        : "+f"(c[0]), "+f"(c[1]), "+f"(c[2]), "+f"(c[3])
        : "r"(a0), "r"(a1), "r"(a2), "r"(a3), "r"(b0), "r"(b1));
}

// split a float4 into hi/lo bf16 and store as two bf162 pairs at smem offset `off`
__device__ __forceinline__ void split_store(__nv_bfloat16* shi, __nv_bfloat16* slo,
                                            int off, float4 v) {
    float va[4] = {v.x, v.y, v.z, v.w};
    __nv_bfloat16 hi[4], lo[4];
    #pragma unroll
    for (int q = 0; q < 4; q++) {
        hi[q] = __float2bfloat16(va[q]);
        lo[q] = __float2bfloat16(va[q] - __bfloat162float(hi[q]));
    }
    *reinterpret_cast<__nv_bfloat162*>(shi + off)     = __halves2bfloat162(hi[0], hi[1]);
    *reinterpret_cast<__nv_bfloat162*>(shi + off + 2) = __halves2bfloat162(hi[2], hi[3]);
    *reinterpret_cast<__nv_bfloat162*>(slo + off)     = __halves2bfloat162(lo[0], lo[1]);
    *reinterpret_cast<__nv_bfloat162*>(slo + off + 2) = __halves2bfloat162(lo[2], lo[3]);
}

// warp-tile MMA sweep over KC columns of hi/lo split tiles.
// A tile rows at wrow..wrow+63, B tile rows at wcol..wcol+31, stride = padded K (bf16 elems)
template<int STRIDE, int KC>
__device__ __forceinline__ void tile_mma(const __nv_bfloat16* sAhi, const __nv_bfloat16* sAlo,
                                         const __nv_bfloat16* sBhi, const __nv_bfloat16* sBlo,
                                         int wrow, int wcol, int lane,
                                         float acc[4][4][4]) {
    const int arow = lane >> 2;        // 0..7
    const int kq   = (lane & 3) * 2;   // 0,2,4,6
    #pragma unroll
    for (int kk = 0; kk < KC; kk += 16) {
        uint32_t ah[4][4], al[4][4];
        #pragma unroll
        for (int i = 0; i < 4; i++) {
            const int base = (wrow + i * 16 + arow) * STRIDE + kk + kq;
            ah[i][0] = lds_u32(sAhi + base);
            ah[i][1] = lds_u32(sAhi + base + 8 * STRIDE);
            ah[i][2] = lds_u32(sAhi + base + 8);
            ah[i][3] = lds_u32(sAhi + base + 8 * STRIDE + 8);
            al[i][0] = lds_u32(sAlo + base);
            al[i][1] = lds_u32(sAlo + base + 8 * STRIDE);
            al[i][2] = lds_u32(sAlo + base + 8);
            al[i][3] = lds_u32(sAlo + base + 8 * STRIDE + 8);
        }
        uint32_t bh[4][2], bl[4][2];
        #pragma unroll
        for (int j = 0; j < 4; j++) {
            const int base = (wcol + j * 8 + arow) * STRIDE + kk + kq;
            bh[j][0] = lds_u32(sBhi + base);
            bh[j][1] = lds_u32(sBhi + base + 8);
            bl[j][0] = lds_u32(sBlo + base);
            bl[j][1] = lds_u32(sBlo + base + 8);
        }
        #pragma unroll
        for (int i = 0; i < 4; i++)
            #pragma unroll
            for (int j = 0; j < 4; j++) {
                mma_bf16(acc[i][j], ah[i][0], ah[i][1], ah[i][2], ah[i][3], bh[j][0], bh[j][1]);
                mma_bf16(acc[i][j], ah[i][0], ah[i][1], ah[i][2], ah[i][3], bl[j][0], bl[j][1]);
                mma_bf16(acc[i][j], al[i][0], al[i][1], al[i][2], al[i][3], bh[j][0], bh[j][1]);
            }
    }
}

// C[M x N] = act( A[M x K] * B[N x K]^T + bias ), fp32 in/out.
// 2-term bf16 split per operand, 3 bf16 MMAs (hi*hi + hi*lo + lo*hi), fp32 accumulate.
// Software-pipelined: next k-tile LDGs issue before the MMA sweep of the current tile.
template<int ACT>
__global__ void __launch_bounds__(NTHREADS, 1)
gemm_nt_split(const float* __restrict__ A, long long strideA, int lda,
              const float* __restrict__ Bm, long long strideB, int ldb,
              const float* __restrict__ bias,
              float* __restrict__ C, long long strideC, int ldc,
              int K)
{
    __shared__ __nv_bfloat16 sAhi[BM * KP];
    __shared__ __nv_bfloat16 sAlo[BM * KP];
    __shared__ __nv_bfloat16 sBhi[BN * KP];
    __shared__ __nv_bfloat16 sBlo[BN * KP];

    const int tid  = threadIdx.x;
    const int lane = tid & 31;
    const int warp = tid >> 5;
    const int wrow = (warp >> 2) * 64;
    const int wcol = (warp & 3) * 32;

    const long long bz = blockIdx.z;
    const float* Ag = A  + bz * strideA + (long long)blockIdx.y * BM * lda;
    const float* Bg = Bm + bz * strideB + (long long)blockIdx.x * BN * ldb;

    const int lr = tid >> 3;         // row 0..31 (+32p)
    const int lc = (tid & 7) * 4;    // float col 0..28

    float acc[4][4][4];
    #pragma unroll
    for (int i = 0; i < 4; i++)
        #pragma unroll
        for (int j = 0; j < 4; j++)
            #pragma unroll
            for (int t = 0; t < 4; t++) acc[i][j][t] = 0.f;

    // prologue: load first k-tile into registers
    float4 ra[4], rb[4];
    #pragma unroll
    for (int p = 0; p < 4; p++) {
        ra[p] = *reinterpret_cast<const float4*>(Ag + (long long)(lr + 32 * p) * lda + lc);
        rb[p] = *reinterpret_cast<const float4*>(Bg + (long long)(lr + 32 * p) * ldb + lc);
    }

    for (int k0 = 0; k0 < K; k0 += BK) {
        __syncthreads();   // previous iteration's MMA readers done with smem
        #pragma unroll
        for (int p = 0; p < 4; p++) {
            const int off = (lr + 32 * p) * KP + lc;
            split_store(sAhi, sAlo, off, ra[p]);
            split_store(sBhi, sBlo, off, rb[p]);
        }
        __syncthreads();   // smem tiles ready

        // prefetch next k-tile: LDGs in flight while the MMA sweep runs
        const bool more = (k0 + BK) < K;
        float4 na[4], nb[4];
        if (more) {
            #pragma unroll
            for (int p = 0; p < 4; p++) {
                na[p] = *reinterpret_cast<const float4*>(Ag + (long long)(lr + 32 * p) * lda + (k0 + BK + lc));
                nb[p] = *reinterpret_cast<const float4*>(Bg + (long long)(lr + 32 * p) * ldb + (k0 + BK + lc));
            }
        }

        tile_mma<KP, BK>(sAhi, sAlo, sBhi, sBlo, wrow, wcol, lane, acc);

        if (more) {
            #pragma unroll
            for (int p = 0; p < 4; p++) { ra[p] = na[p]; rb[p] = nb[p]; }
        }
    }

    // epilogue: bias + optional relu, fp32 store
    float* Cg = C + bz * strideC;
    const int rb0 = blockIdx.y * BM + wrow;
    const int cb0 = blockIdx.x * BN + wcol;
    #pragma unroll
    for (int i = 0; i < 4; i++) {
        const int r0 = rb0 + i * 16 + (lane >> 2);
        #pragma unroll
        for (int j = 0; j < 4; j++) {
            const int c0 = cb0 + j * 8 + (lane & 3) * 2;
            float v0 = acc[i][j][0], v1 = acc[i][j][1], v2 = acc[i][j][2], v3 = acc[i][j][3];
            if (bias) {
                const float bb0 = bias[c0], bb1 = bias[c0 + 1];
                v0 += bb0; v1 += bb1; v2 += bb0; v3 += bb1;
            }
            if (ACT) {
                v0 = fmaxf(v0, 0.f); v1 = fmaxf(v1, 0.f);
                v2 = fmaxf(v2, 0.f); v3 = fmaxf(v3, 0.f);
            }
            *reinterpret_cast<float2*>(Cg + (long long)r0 * ldc + c0)       = make_float2(v0, v1);
            *reinterpret_cast<float2*>(Cg + (long long)(r0 + 8) * ldc + c0) = make_float2(v2, v3);
        }
    }
}

// -------- fused MLP: m2 = relu(relu(h W1^T + b1) W2^T + b2) --------
// One CTA per 128 rows. K=128 lives entirely in smem; m1 never touches HBM.
// Dynamic smem: 4 arrays of [128][KP2] bf16 = 139,264 bytes.
extern __shared__ __nv_bfloat16 s_dyn[];

__global__ void __launch_bounds__(NTHREADS, 1)
mlp_fused(const float* __restrict__ h,
          const float* __restrict__ W1, const float* __restrict__ b1,
          const float* __restrict__ W2, const float* __restrict__ b2,
          float* __restrict__ m2)
{
    __nv_bfloat16* sXhi = s_dyn;
    __nv_bfloat16* sXlo = sXhi + 128 * KP2;
    __nv_bfloat16* sWhi = sXlo + 128 * KP2;
    __nv_bfloat16* sWlo = sWhi + 128 * KP2;

    const int tid  = threadIdx.x;
    const int lane = tid & 31;
    const int warp = tid >> 5;
    const int wrow = (warp >> 2) * 64;
    const int wcol = (warp & 3) * 32;

    const float* Xg = h + (long long)blockIdx.x * 128 * H_;

    // load + split X (h rows) and W1: 128x128 fp32 each -> 4096 float4 each
    #pragma unroll
    for (int it = 0; it < 16; it++) {
        const int i   = tid + it * NTHREADS;      // 0..4095
        const int row = i >> 5;
        const int c4  = (i & 31) * 4;
        const int off = row * KP2 + c4;
        split_store(sXhi, sXlo, off, *reinterpret_cast<const float4*>(Xg + row * H_ + c4));
        split_store(sWhi, sWlo, off, *reinterpret_cast<const float4*>(W1 + row * H_ + c4));
    }
    __syncthreads();

    float acc[4][4][4];
    #pragma unroll
    for (int i = 0; i < 4; i++)
        #pragma unroll
        for (int j = 0; j < 4; j++)
            #pragma unroll
            for (int t = 0; t < 4; t++) acc[i][j][t] = 0.f;

    // ---- gemm1: X @ W1^T ----
    tile_mma<KP2, 128>(sXhi, sXlo, sWhi, sWlo, wrow, wcol, lane, acc);
    __syncthreads();   // all warps done reading sX / sW before overwrite

    // relu(acc + b1) -> split back into sX (becomes m1 tile)
    #pragma unroll
    for (int i = 0; i < 4; i++) {
        const int row = wrow + i * 16 + (lane >> 2);
        #pragma unroll
        for (int j = 0; j < 4; j++) {
            const int col = wcol + j * 8 + (lane & 3) * 2;
            const float bb0 = b1[col], bb1 = b1[col + 1];
            float v0 = fmaxf(acc[i][j][0] + bb0, 0.f);
            float v1 = fmaxf(acc[i][j][1] + bb1, 0.f);
            float v2 = fmaxf(acc[i][j][2] + bb0, 0.f);
            float v3 = fmaxf(acc[i][j][3] + bb1, 0.f);
            __nv_bfloat16 h0 = __float2bfloat16(v0), h1 = __float2bfloat16(v1);
            __nv_bfloat16 h2 = __float2bfloat16(v2), h3 = __float2bfloat16(v3);
            __nv_bfloat16 l0 = __float2bfloat16(v0 - __bfloat162float(h0));
            __nv_bfloat16 l1 = __float2bfloat16(v1 - __bfloat162float(h1));
            __nv_bfloat16 l2 = __float2bfloat16(v2 - __bfloat162float(h2));
            __nv_bfloat16 l3 = __float2bfloat16(v3 - __bfloat162float(h3));
            *reinterpret_cast<__nv_bfloat162*>(sXhi + row * KP2 + col)       = __halves2bfloat162(h0, h1);
            *reinterpret_cast<__nv_bfloat162*>(sXlo + row * KP2 + col)       = __halves2bfloat162(l0, l1);
            *reinterpret_cast<__nv_bfloat162*>(sXhi + (row + 8) * KP2 + col) = __halves2bfloat162(h2, h3);
            *reinterpret_cast<__nv_bfloat162*>(sXlo + (row + 8) * KP2 + col) = __halves2bfloat162(l2, l3);
            // reset acc for gemm2
            acc[i][j][0] = acc[i][j][1] = acc[i][j][2] = acc[i][j][3] = 0.f;
        }
    }

    // load + split W2 (overwrites W1 tile)
    #pragma unroll
    for (int it = 0; it < 16; it++) {
        const int i   = tid + it * NTHREADS;
        const int row = i >> 5;
        const int c4  = (i & 31) * 4;
        split_store(sWhi, sWlo, row * KP2 + c4, *reinterpret_cast<const float4*>(W2 + row * H_ + c4));
    }
    __syncthreads();

    // ---- gemm2: m1 @ W2^T ----
    tile_mma<KP2, 128>(sXhi, sXlo, sWhi, sWlo, wrow, wcol, lane, acc);

    // relu(acc + b2) -> m2 global
    float* Cg = m2 + (long long)blockIdx.x * 128 * H_;
    #pragma unroll
    for (int i = 0; i < 4; i++) {
        const int row = wrow + i * 16 + (lane >> 2);
        #pragma unroll
        for (int j = 0; j < 4; j++) {
            const int col = wcol + j * 8 + (lane & 3) * 2;
            const float bb0 = b2[col], bb1 = b2[col + 1];
            float v0 = fmaxf(acc[i][j][0] + bb0, 0.f);
            float v1 = fmaxf(acc[i][j][1] + bb1, 0.f);
            float v2 = fmaxf(acc[i][j][2] + bb0, 0.f);
            float v3 = fmaxf(acc[i][j][3] + bb1, 0.f);
            *reinterpret_cast<float2*>(Cg + (long long)row * H_ + col)       = make_float2(v0, v1);
            *reinterpret_cast<float2*>(Cg + (long long)(row + 8) * H_ + col) = make_float2(v2, v3);
        }
    }
}

// transpose m2 [b][n][h] -> mt [b][h][n]   (so the adjacency gemm is also NT)
__global__ void transpose_m(const float* __restrict__ src, float* __restrict__ dst)
{
    __shared__ float t[32][33];
    const int b  = blockIdx.z;
    const int n0 = blockIdx.x * 32;
    const int h0 = blockIdx.y * 32;
    const float* s = src + (long long)b * N_ * H_;
    float* d       = dst + (long long)b * H_ * N_;
    const int tx = threadIdx.x, ty = threadIdx.y;  // 32 x 8
    #pragma unroll
    for (int i = 0; i < 32; i += 8)
        t[ty + i][tx] = s[(long long)(n0 + ty + i) * H_ + h0 + tx];
    __syncthreads();
    #pragma unroll
    for (int i = 0; i < 32; i += 8)
        d[(long long)(h0 + ty + i) * N_ + n0 + tx] = t[tx][ty + i];
}

// GRU gate combine (torch GRUCell order r,z,n), vectorized float4
__global__ void gru_gates(const float* __restrict__ gx, const float* __restrict__ gh,
                          const float* __restrict__ h, float* __restrict__ out)
{
    const int idx4 = blockIdx.x * blockDim.x + threadIdx.x;
    if (idx4 >= R_ * H_ / 4) return;
    const int i  = idx4 >> 5;            // row
    const int j4 = (idx4 & 31) * 4;      // col
    const float* gxr = gx + (long long)i * 3 * H_;
    const float* ghr = gh + (long long)i * 3 * H_;
    const float4 xr = *reinterpret_cast<const float4*>(gxr + j4);
    const float4 xz = *reinterpret_cast<const float4*>(gxr + j4 + H_);
    const float4 xn = *reinterpret_cast<const float4*>(gxr + j4 + 2 * H_);
    const float4 hr = *reinterpret_cast<const float4*>(ghr + j4);
    const float4 hz = *reinterpret_cast<const float4*>(ghr + j4 + H_);
    const float4 hn = *reinterpret_cast<const float4*>(ghr + j4 + 2 * H_);
    const float4 hv = *reinterpret_cast<const float4*>(h + (long long)i * H_ + j4);

    float4 o;
    {
        const float r = 1.f / (1.f + expf(-(xr.x + hr.x)));
        const float z = 1.f / (1.f + expf(-(xz.x + hz.x)));
        const float n = tanhf(xn.x + r * hn.x);
        o.x = (1.f - z) * n + z * hv.x;
    }
    {
        const float r = 1.f / (1.f + expf(-(xr.y + hr.y)));
        const float z = 1.f / (1.f + expf(-(xz.y + hz.y)));
        const float n = tanhf(xn.y + r * hn.y);
        o.y = (1.f - z) * n + z * hv.y;
    }
    {
        const float r = 1.f / (1.f + expf(-(xr.z + hr.z)));
        const float z = 1.f / (1.f + expf(-(xz.z + hz.z)));
        const float n = tanhf(xn.z + r * hn.z);
        o.z = (1.f - z) * n + z * hv.z;
    }
    {
        const float r = 1.f / (1.f + expf(-(xr.w + hr.w)));
        const float z = 1.f / (1.f + expf(-(xz.w + hz.w)));
        const float n = tanhf(xn.w + r * hn.w);
        o.w = (1.f - z) * n + z * hv.w;
    }
    *reinterpret_cast<float4*>(out + (long long)i * H_ + j4) = o;
}

extern "C" void kernel_launch(void* const* d_in, const int* in_sizes, int n_in,
                              void* d_out, int out_size)
{
    const float* h   = (const float*)d_in[0];   // [8,2048,128]
    const float* A   = (const float*)d_in[1];   // [8,2048,2048]
    const float* W1  = (const float*)d_in[2];   // [128,128]
    const float* b1  = (const float*)d_in[3];   // [128]
    const float* W2  = (const float*)d_in[4];   // [128,128]
    const float* b2  = (const float*)d_in[5];   // [128]
    const float* Wih = (const float*)d_in[6];   // [384,128]
    const float* Whh = (const float*)d_in[7];   // [384,128]
    const float* bih = (const float*)d_in[8];   // [384]
    const float* bhh = (const float*)d_in[9];   // [384]
    float* out = (float*)d_out;                 // [8,2048,128]

    float *m2, *mt, *msg, *gx, *gh;
    cudaGetSymbolAddress((void**)&m2,  g_m2);
    cudaGetSymbolAddress((void**)&mt,  g_mt);
    cudaGetSymbolAddress((void**)&msg, g_msg);
    cudaGetSymbolAddress((void**)&gx,  g_gx);
    cudaGetSymbolAddress((void**)&gh,  g_gh);

    const dim3 blk(NTHREADS);
    const int MLP_SMEM = 4 * 128 * KP2 * (int)sizeof(__nv_bfloat16);  // 139264

    static bool attr_done = false;
    cudaFuncSetAttribute(mlp_fused, cudaFuncAttributeMaxDynamicSharedMemorySize, MLP_SMEM);
    (void)attr_done;

    // 1+2) fused MLP: m2 = relu(relu(h W1^T + b1) W2^T + b2)
    mlp_fused<<<dim3(R_ / 128), blk, MLP_SMEM>>>(h, W1, b1, W2, b2, m2);

    // 3) mt[b][h][n] = m2[b][n][h]
    transpose_m<<<dim3(N_ / 32, H_ / 32, B_), dim3(32, 8)>>>(m2, mt);

    // 4) msg = relu(A_b @ m_b)  per batch: M=2048, N=128, K=2048 (NT vs mt)
    gemm_nt_split<1><<<dim3(1, N_ / BM, B_), blk>>>(
        A,  (long long)N_ * N_, N_,
        mt, (long long)H_ * N_, N_,
        nullptr,
        msg, (long long)N_ * H_, H_, N_);

    // 5) gx = msg @ W_ih^T + b_ih   [16384 x 384]
    gemm_nt_split<0><<<dim3(3 * H_ / BN, R_ / BM, 1), blk>>>(
        msg, 0, H_, Wih, 0, H_, bih, gx, 0, 3 * H_, H_);

    // 6) gh = h @ W_hh^T + b_hh
    gemm_nt_split<0><<<dim3(3 * H_ / BN, R_ / BM, 1), blk>>>(
        h, 0, H_, Whh, 0, H_, bhh, gh, 0, 3 * H_, H_);

    // 7) gates + output
    gru_gates<<<(R_ * H_ / 4 + 255) / 256, 256>>>(gx, gh, h, out);
}

// round 10
// speedup vs baseline: 1.3164x; 1.0033x over previous
#include <cuda_runtime.h>
#include <cuda_bf16.h>
#include <stdint.h>

// Problem dims (fixed by the reference)
#define B_  8
#define N_  2048
#define H_  128
#define R_  (B_ * N_)   // 16384 total rows

// GEMM tiling
#define BM 128
#define BN 128
#define BK 32
#define KP 40           // padded K stride (bf16) for BK=32 tiles -> conflict-free
#define KP2 136         // padded K stride (bf16) for K=128 resident tiles
#define NTHREADS 256

// -------- scratch (__device__ globals: no allocation allowed) --------
__device__ float g_m2 [R_ * H_];        // 8 MB
__device__ float g_mt [B_ * H_ * N_];   // 8 MB   (m2 transposed per batch: [b][h][n])
__device__ float g_msg[R_ * H_];        // 8 MB
__device__ float g_gx [R_ * 3 * H_];    // 24 MB
__device__ float g_gh [R_ * 3 * H_];    // 24 MB

__device__ __forceinline__ uint32_t lds_u32(const __nv_bfloat16* p) {
    return *reinterpret_cast<const uint32_t*>(p);
}

__device__ __forceinline__ void mma_bf16(float* c,
                                         uint32_t a0, uint32_t a1, uint32_t a2, uint32_t a3,
                                         uint32_t b0, uint32_t b1) {
    asm volatile(
        "mma.sync.aligned.m16n8k16.row.col.f32.bf16.bf16.f32 "
        "{%0,%1,%2,%3}, {%4,%5,%6,%7}, {%8,%9}, {%0,%1,%2,%3};\n"
        : "+f"(c[0]), "+f"(c[1]), "+f"(c[2]), "+f"(c[3])
        : "r"(a0), "r"(a1), "r"(a2), "r"(a3), "r"(b0), "r"(b1));
}

// split a float4 into hi/lo bf16 and store as two bf162 pairs at smem offset `off`
__device__ __forceinline__ void split_store(__nv_bfloat16* shi, __nv_bfloat16* slo,
                                            int off, float4 v) {
    float va[4] = {v.x, v.y, v.z, v.w};
    __nv_bfloat16 hi[4], lo[4];
    #pragma unroll
    for (int q = 0; q < 4; q++) {
        hi[q] = __float2bfloat16(va[q]);
        lo[q] = __float2bfloat16(va[q] - __bfloat162float(hi[q]));
    }
    *reinterpret_cast<__nv_bfloat162*>(shi + off)     = __halves2bfloat162(hi[0], hi[1]);
    *reinterpret_cast<__nv_bfloat162*>(shi + off + 2) = __halves2bfloat162(hi[2], hi[3]);
    *reinterpret_cast<__nv_bfloat162*>(slo + off)     = __halves2bfloat162(lo[0], lo[1]);
    *reinterpret_cast<__nv_bfloat162*>(slo + off + 2) = __halves2bfloat162(lo[2], lo[3]);
}

// warp-tile MMA sweep over KC columns of hi/lo split tiles.
// A tile rows at wrow..wrow+63, B tile rows at wcol..wcol+31, stride = padded K (bf16 elems)
template<int STRIDE, int KC>
__device__ __forceinline__ void tile_mma(const __nv_bfloat16* sAhi, const __nv_bfloat16* sAlo,
                                         const __nv_bfloat16* sBhi, const __nv_bfloat16* sBlo,
                                         int wrow, int wcol, int lane,
                                         float acc[4][4][4]) {
    const int arow = lane >> 2;        // 0..7
    const int kq   = (lane & 3) * 2;   // 0,2,4,6
    #pragma unroll
    for (int kk = 0; kk < KC; kk += 16) {
        uint32_t ah[4][4], al[4][4];
        #pragma unroll
        for (int i = 0; i < 4; i++) {
            const int base = (wrow + i * 16 + arow) * STRIDE + kk + kq;
            ah[i][0] = lds_u32(sAhi + base);
            ah[i][1] = lds_u32(sAhi + base + 8 * STRIDE);
            ah[i][2] = lds_u32(sAhi + base + 8);
            ah[i][3] = lds_u32(sAhi + base + 8 * STRIDE + 8);
            al[i][0] = lds_u32(sAlo + base);
            al[i][1] = lds_u32(sAlo + base + 8 * STRIDE);
            al[i][2] = lds_u32(sAlo + base + 8);
            al[i][3] = lds_u32(sAlo + base + 8 * STRIDE + 8);
        }
        uint32_t bh[4][2], bl[4][2];
        #pragma unroll
        for (int j = 0; j < 4; j++) {
            const int base = (wcol + j * 8 + arow) * STRIDE + kk + kq;
            bh[j][0] = lds_u32(sBhi + base);
            bh[j][1] = lds_u32(sBhi + base + 8);
            bl[j][0] = lds_u32(sBlo + base);
            bl[j][1] = lds_u32(sBlo + base + 8);
        }
        #pragma unroll
        for (int i = 0; i < 4; i++)
            #pragma unroll
            for (int j = 0; j < 4; j++) {
                mma_bf16(acc[i][j], ah[i][0], ah[i][1], ah[i][2], ah[i][3], bh[j][0], bh[j][1]);
                mma_bf16(acc[i][j], ah[i][0], ah[i][1], ah[i][2], ah[i][3], bl[j][0], bl[j][1]);
                mma_bf16(acc[i][j], al[i][0], al[i][1], al[i][2], al[i][3], bh[j][0], bh[j][1]);
            }
    }
}

// C[M x N] = act( A[M x K] * B[N x K]^T + bias ), fp32 in/out.
// 2-term bf16 split per operand, 3 bf16 MMAs (hi*hi + hi*lo + lo*hi), fp32 accumulate.
// Software-pipelined: next k-tile LDGs issue before the MMA sweep of the current tile.
template<int ACT>
__global__ void __launch_bounds__(NTHREADS, 1)
gemm_nt_split(const float* __restrict__ A, long long strideA, int lda,
              const float* __restrict__ Bm, long long strideB, int ldb,
              const float* __restrict__ bias,
              float* __restrict__ C, long long strideC, int ldc,
              int K)
{
    __shared__ __nv_bfloat16 sAhi[BM * KP];
    __shared__ __nv_bfloat16 sAlo[BM * KP];
    __shared__ __nv_bfloat16 sBhi[BN * KP];
    __shared__ __nv_bfloat16 sBlo[BN * KP];

    const int tid  = threadIdx.x;
    const int lane = tid & 31;
    const int warp = tid >> 5;
    const int wrow = (warp >> 2) * 64;
    const int wcol = (warp & 3) * 32;

    const long long bz = blockIdx.z;
    const float* Ag = A  + bz * strideA + (long long)blockIdx.y * BM * lda;
    const float* Bg = Bm + bz * strideB + (long long)blockIdx.x * BN * ldb;

    const int lr = tid >> 3;         // row 0..31 (+32p)
    const int lc = (tid & 7) * 4;    // float col 0..28

    float acc[4][4][4];
    #pragma unroll
    for (int i = 0; i < 4; i++)
        #pragma unroll
        for (int j = 0; j < 4; j++)
            #pragma unroll
            for (int t = 0; t < 4; t++) acc[i][j][t] = 0.f;

    // prologue: load first k-tile into registers
    float4 ra[4], rb[4];
    #pragma unroll
    for (int p = 0; p < 4; p++) {
        ra[p] = *reinterpret_cast<const float4*>(Ag + (long long)(lr + 32 * p) * lda + lc);
        rb[p] = *reinterpret_cast<const float4*>(Bg + (long long)(lr + 32 * p) * ldb + lc);
    }

    for (int k0 = 0; k0 < K; k0 += BK) {
        __syncthreads();   // previous iteration's MMA readers done with smem
        #pragma unroll
        for (int p = 0; p < 4; p++) {
            const int off = (lr + 32 * p) * KP + lc;
            split_store(sAhi, sAlo, off, ra[p]);
            split_store(sBhi, sBlo, off, rb[p]);
        }
        __syncthreads();   // smem tiles ready

        // prefetch next k-tile: LDGs in flight while the MMA sweep runs
        const bool more = (k0 + BK) < K;
        float4 na[4], nb[4];
        if (more) {
            #pragma unroll
            for (int p = 0; p < 4; p++) {
                na[p] = *reinterpret_cast<const float4*>(Ag + (long long)(lr + 32 * p) * lda + (k0 + BK + lc));
                nb[p] = *reinterpret_cast<const float4*>(Bg + (long long)(lr + 32 * p) * ldb + (k0 + BK + lc));
            }
        }

        tile_mma<KP, BK>(sAhi, sAlo, sBhi, sBlo, wrow, wcol, lane, acc);

        if (more) {
            #pragma unroll
            for (int p = 0; p < 4; p++) { ra[p] = na[p]; rb[p] = nb[p]; }
        }
    }

    // epilogue: bias + optional relu, fp32 store
    float* Cg = C + bz * strideC;
    const int rb0 = blockIdx.y * BM + wrow;
    const int cb0 = blockIdx.x * BN + wcol;
    #pragma unroll
    for (int i = 0; i < 4; i++) {
        const int r0 = rb0 + i * 16 + (lane >> 2);
        #pragma unroll
        for (int j = 0; j < 4; j++) {
            const int c0 = cb0 + j * 8 + (lane & 3) * 2;
            float v0 = acc[i][j][0], v1 = acc[i][j][1], v2 = acc[i][j][2], v3 = acc[i][j][3];
            if (bias) {
                const float bb0 = bias[c0], bb1 = bias[c0 + 1];
                v0 += bb0; v1 += bb1; v2 += bb0; v3 += bb1;
            }
            if (ACT) {
                v0 = fmaxf(v0, 0.f); v1 = fmaxf(v1, 0.f);
                v2 = fmaxf(v2, 0.f); v3 = fmaxf(v3, 0.f);
            }
            *reinterpret_cast<float2*>(Cg + (long long)r0 * ldc + c0)       = make_float2(v0, v1);
            *reinterpret_cast<float2*>(Cg + (long long)(r0 + 8) * ldc + c0) = make_float2(v2, v3);
        }
    }
}

// -------- fused MLP: m2 = relu(relu(h W1^T + b1) W2^T + b2) --------
// One CTA per 128 rows. K=128 lives entirely in smem; m1 never touches HBM.
// Dynamic smem: 4 arrays of [128][KP2] bf16 = 139,264 bytes.
extern __shared__ __nv_bfloat16 s_dyn[];

__global__ void __launch_bounds__(NTHREADS, 1)
mlp_fused(const float* __restrict__ h,
          const float* __restrict__ W1, const float* __restrict__ b1,
          const float* __restrict__ W2, const float* __restrict__ b2,
          float* __restrict__ m2)
{
    __nv_bfloat16* sXhi = s_dyn;
    __nv_bfloat16* sXlo = sXhi + 128 * KP2;
    __nv_bfloat16* sWhi = sXlo + 128 * KP2;
    __nv_bfloat16* sWlo = sWhi + 128 * KP2;

    const int tid  = threadIdx.x;
    const int lane = tid & 31;
    const int warp = tid >> 5;
    const int wrow = (warp >> 2) * 64;
    const int wcol = (warp & 3) * 32;

    const float* Xg = h + (long long)blockIdx.x * 128 * H_;

    // load + split X (h rows) and W1: 128x128 fp32 each -> 4096 float4 each
    #pragma unroll
    for (int it = 0; it < 16; it++) {
        const int i   = tid + it * NTHREADS;      // 0..4095
        const int row = i >> 5;
        const int c4  = (i & 31) * 4;
        const int off = row * KP2 + c4;
        split_store(sXhi, sXlo, off, *reinterpret_cast<const float4*>(Xg + row * H_ + c4));
        split_store(sWhi, sWlo, off, *reinterpret_cast<const float4*>(W1 + row * H_ + c4));
    }
    __syncthreads();

    float acc[4][4][4];
    #pragma unroll
    for (int i = 0; i < 4; i++)
        #pragma unroll
        for (int j = 0; j < 4; j++)
            #pragma unroll
            for (int t = 0; t < 4; t++) acc[i][j][t] = 0.f;

    // ---- gemm1: X @ W1^T ----
    tile_mma<KP2, 128>(sXhi, sXlo, sWhi, sWlo, wrow, wcol, lane, acc);
    __syncthreads();   // all warps done reading sX / sW before overwrite

    // relu(acc + b1) -> split back into sX (becomes m1 tile)
    #pragma unroll
    for (int i = 0; i < 4; i++) {
        const int row = wrow + i * 16 + (lane >> 2);
        #pragma unroll
        for (int j = 0; j < 4; j++) {
            const int col = wcol + j * 8 + (lane & 3) * 2;
            const float bb0 = b1[col], bb1 = b1[col + 1];
            float v0 = fmaxf(acc[i][j][0] + bb0, 0.f);
            float v1 = fmaxf(acc[i][j][1] + bb1, 0.f);
            float v2 = fmaxf(acc[i][j][2] + bb0, 0.f);
            float v3 = fmaxf(acc[i][j][3] + bb1, 0.f);
            __nv_bfloat16 h0 = __float2bfloat16(v0), h1 = __float2bfloat16(v1);
            __nv_bfloat16 h2 = __float2bfloat16(v2), h3 = __float2bfloat16(v3);
            __nv_bfloat16 l0 = __float2bfloat16(v0 - __bfloat162float(h0));
            __nv_bfloat16 l1 = __float2bfloat16(v1 - __bfloat162float(h1));
            __nv_bfloat16 l2 = __float2bfloat16(v2 - __bfloat162float(h2));
            __nv_bfloat16 l3 = __float2bfloat16(v3 - __bfloat162float(h3));
            *reinterpret_cast<__nv_bfloat162*>(sXhi + row * KP2 + col)       = __halves2bfloat162(h0, h1);
            *reinterpret_cast<__nv_bfloat162*>(sXlo + row * KP2 + col)       = __halves2bfloat162(l0, l1);
            *reinterpret_cast<__nv_bfloat162*>(sXhi + (row + 8) * KP2 + col) = __halves2bfloat162(h2, h3);
            *reinterpret_cast<__nv_bfloat162*>(sXlo + (row + 8) * KP2 + col) = __halves2bfloat162(l2, l3);
            // reset acc for gemm2
            acc[i][j][0] = acc[i][j][1] = acc[i][j][2] = acc[i][j][3] = 0.f;
        }
    }

    // load + split W2 (overwrites W1 tile)
    #pragma unroll
    for (int it = 0; it < 16; it++) {
        const int i   = tid + it * NTHREADS;
        const int row = i >> 5;
        const int c4  = (i & 31) * 4;
        split_store(sWhi, sWlo, row * KP2 + c4, *reinterpret_cast<const float4*>(W2 + row * H_ + c4));
    }
    __syncthreads();

    // ---- gemm2: m1 @ W2^T ----
    tile_mma<KP2, 128>(sXhi, sXlo, sWhi, sWlo, wrow, wcol, lane, acc);

    // relu(acc + b2) -> m2 global
    float* Cg = m2 + (long long)blockIdx.x * 128 * H_;
    #pragma unroll
    for (int i = 0; i < 4; i++) {
        const int row = wrow + i * 16 + (lane >> 2);
        #pragma unroll
        for (int j = 0; j < 4; j++) {
            const int col = wcol + j * 8 + (lane & 3) * 2;
            const float bb0 = b2[col], bb1 = b2[col + 1];
            float v0 = fmaxf(acc[i][j][0] + bb0, 0.f);
            float v1 = fmaxf(acc[i][j][1] + bb1, 0.f);
            float v2 = fmaxf(acc[i][j][2] + bb0, 0.f);
            float v3 = fmaxf(acc[i][j][3] + bb1, 0.f);
            *reinterpret_cast<float2*>(Cg + (long long)row * H_ + col)       = make_float2(v0, v1);
            *reinterpret_cast<float2*>(Cg + (long long)(row + 8) * H_ + col) = make_float2(v2, v3);
        }
    }
}

// transpose m2 [b][n][h] -> mt [b][h][n]   (so the adjacency gemm is also NT)
__global__ void transpose_m(const float* __restrict__ src, float* __restrict__ dst)
{
    __shared__ float t[32][33];
    const int b  = blockIdx.z;
    const int n0 = blockIdx.x * 32;
    const int h0 = blockIdx.y * 32;
    const float* s = src + (long long)b * N_ * H_;
    float* d       = dst + (long long)b * H_ * N_;
    const int tx = threadIdx.x, ty = threadIdx.y;  // 32 x 8
    #pragma unroll
    for (int i = 0; i < 32; i += 8)
        t[ty + i][tx] = s[(long long)(n0 + ty + i) * H_ + h0 + tx];
    __syncthreads();
    #pragma unroll
    for (int i = 0; i < 32; i += 8)
        d[(long long)(h0 + ty + i) * N_ + n0 + tx] = t[tx][ty + i];
}

// GRU gate combine (torch GRUCell order r,z,n), vectorized float4
__global__ void gru_gates(const float* __restrict__ gx, const float* __restrict__ gh,
                          const float* __restrict__ h, float* __restrict__ out)
{
    const int idx4 = blockIdx.x * blockDim.x + threadIdx.x;
    if (idx4 >= R_ * H_ / 4) return;
    const int i  = idx4 >> 5;            // row
    const int j4 = (idx4 & 31) * 4;      // col
    const float* gxr = gx + (long long)i * 3 * H_;
    const float* ghr = gh + (long long)i * 3 * H_;
    const float4 xr = *reinterpret_cast<const float4*>(gxr + j4);
    const float4 xz = *reinterpret_cast<const float4*>(gxr + j4 + H_);
    const float4 xn = *reinterpret_cast<const float4*>(gxr + j4 + 2 * H_);
    const float4 hr = *reinterpret_cast<const float4*>(ghr + j4);
    const float4 hz = *reinterpret_cast<const float4*>(ghr + j4 + H_);
    const float4 hn = *reinterpret_cast<const float4*>(ghr + j4 + 2 * H_);
    const float4 hv = *reinterpret_cast<const float4*>(h + (long long)i * H_ + j4);

    float4 o;
    {
        const float r = 1.f / (1.f + expf(-(xr.x + hr.x)));
        const float z = 1.f / (1.f + expf(-(xz.x + hz.x)));
        const float n = tanhf(xn.x + r * hn.x);
        o.x = (1.f - z) * n + z * hv.x;
    }
    {
        const float r = 1.f / (1.f + expf(-(xr.y + hr.y)));
        const float z = 1.f / (1.f + expf(-(xz.y + hz.y)));
        const float n = tanhf(xn.y + r * hn.y);
        o.y = (1.f - z) * n + z * hv.y;
    }
    {
        const float r = 1.f / (1.f + expf(-(xr.z + hr.z)));
        const float z = 1.f / (1.f + expf(-(xz.z + hz.z)));
        const float n = tanhf(xn.z + r * hn.z);
        o.z = (1.f - z) * n + z * hv.z;
    }
    {
        const float r = 1.f / (1.f + expf(-(xr.w + hr.w)));
        const float z = 1.f / (1.f + expf(-(xz.w + hz.w)));
        const float n = tanhf(xn.w + r * hn.w);
        o.w = (1.f - z) * n + z * hv.w;
    }
    *reinterpret_cast<float4*>(out + (long long)i * H_ + j4) = o;
}

extern "C" void kernel_launch(void* const* d_in, const int* in_sizes, int n_in,
                              void* d_out, int out_size)
{
    const float* h   = (const float*)d_in[0];   // [8,2048,128]
    const float* A   = (const float*)d_in[1];   // [8,2048,2048]
    const float* W1  = (const float*)d_in[2];   // [128,128]
    const float* b1  = (const float*)d_in[3];   // [128]
    const float* W2  = (const float*)d_in[4];   // [128,128]
    const float* b2  = (const float*)d_in[5];   // [128]
    const float* Wih = (const float*)d_in[6];   // [384,128]
    const float* Whh = (const float*)d_in[7];   // [384,128]
    const float* bih = (const float*)d_in[8];   // [384]
    const float* bhh = (const float*)d_in[9];   // [384]
    float* out = (float*)d_out;                 // [8,2048,128]

    float *m2, *mt, *msg, *gx, *gh;
    cudaGetSymbolAddress((void**)&m2,  g_m2);
    cudaGetSymbolAddress((void**)&mt,  g_mt);
    cudaGetSymbolAddress((void**)&msg, g_msg);
    cudaGetSymbolAddress((void**)&gx,  g_gx);
    cudaGetSymbolAddress((void**)&gh,  g_gh);

    const dim3 blk(NTHREADS);
    const int MLP_SMEM = 4 * 128 * KP2 * (int)sizeof(__nv_bfloat16);  // 139264

    static bool attr_done = false;
    cudaFuncSetAttribute(mlp_fused, cudaFuncAttributeMaxDynamicSharedMemorySize, MLP_SMEM);
    (void)attr_done;

    // 1+2) fused MLP: m2 = relu(relu(h W1^T + b1) W2^T + b2)
    mlp_fused<<<dim3(R_ / 128), blk, MLP_SMEM>>>(h, W1, b1, W2, b2, m2);

    // 3) mt[b][h][n] = m2[b][n][h]
    transpose_m<<<dim3(N_ / 32, H_ / 32, B_), dim3(32, 8)>>>(m2, mt);

    // 4) msg = relu(A_b @ m_b)  per batch: M=2048, N=128, K=2048 (NT vs mt)
    gemm_nt_split<1><<<dim3(1, N_ / BM, B_), blk>>>(
        A,  (long long)N_ * N_, N_,
        mt, (long long)H_ * N_, N_,
        nullptr,
        msg, (long long)N_ * H_, H_, N_);

    // 5) gx = msg @ W_ih^T + b_ih   [16384 x 384]
    gemm_nt_split<0><<<dim3(3 * H_ / BN, R_ / BM, 1), blk>>>(
        msg, 0, H_, Wih, 0, H_, bih, gx, 0, 3 * H_, H_);

    // 6) gh = h @ W_hh^T + b_hh
    gemm_nt_split<0><<<dim3(3 * H_ / BN, R_ / BM, 1), blk>>>(
        h, 0, H_, Whh, 0, H_, bhh, gh, 0, 3 * H_, H_);

    // 7) gates + output
    gru_gates<<<(R_ * H_ / 4 + 255) / 256, 256>>>(gx, gh, h, out);
}